// round 13
// baseline (speedup 1.0000x reference)
#include <cuda_runtime.h>

#define FULLMASK 0xffffffffu
#define NEGC (-1000000000.0f)
#define FLR  (1e-30f)
#define BIGNEG (-3.0e38f)

__device__ float g_beta[256 * 128 * 128 * 3];   // beta scratch (50.3 MB)

__device__ __forceinline__ float lse2(float a, float b) {
    float mx = fmaxf(a, b);
    float mn = fminf(a, b);
    return mx + __logf(1.0f + __expf(mn - mx));
}
__device__ __forceinline__ float fmax3(float a, float b, float c) {
    return fmaxf(fmaxf(a, b), c);
}
__device__ __forceinline__ void relstore(int* p, int v) {
    asm volatile("st.release.cta.b32 [%0], %1;" :: "l"(p), "r"(v) : "memory");
}
__device__ __forceinline__ int acqload(int* p) {
    int v; asm volatile("ld.acquire.cta.b32 %0, [%1];" : "=r"(v) : "l"(p) : "memory");
    return v;
}

// One CTA (8 warps) per batch. Warps 0-3: forward alpha (cols 32s..32s+31,
// 1 col/lane, left->right mailbox chain) -> out. Warps 4-7: beta lattice
// (independent), right->left chain -> g_beta. y-recurrence per row via
// single-reference softmax scan. Mailboxes carry (m,x,y,q) so the consumer's
// seed tail is one shared-exp LSE3. Then coalesced combine.
__global__ void __launch_bounds__(256, 1)
fb_kernel(const float* __restrict__ theta, const float* __restrict__ Aall,
          float* __restrict__ out)
{
    __shared__ float fm[3][128], fx[3][128], fy[3][128], fq[3][128];
    __shared__ int   ff[3][128];
    __shared__ float bu0s[3][128], bu2s[3][128];
    __shared__ int   bf[3][128];
    __shared__ float shlogZ;

    const int tid  = threadIdx.x;
    const int w    = tid >> 5;
    const int lane = tid & 31;
    const int b    = blockIdx.x;

    for (int j = tid; j < 3 * 128; j += 256) {
        (&ff[0][0])[j] = 0;
        (&bf[0][0])[j] = 0;
    }
    __syncthreads();

    const float* Ab = Aall + (size_t)b * 9;
    const float A02 = Ab[2], A12 = Ab[5], A20 = Ab[6], A21 = Ab[7], A22 = Ab[8];
    float E[9];
#pragma unroll
    for (int t = 0; t < 9; t++) E[t] = __expf(Ab[t]);
    const float eM0 = E[0], eM1 = E[3], eM2 = E[6];   // exp(A[:,0])
    const float eX0 = E[1], eX1 = E[4], eX2 = E[7];   // exp(A[:,1])

    const size_t base_off = (size_t)b * 49152;
    const float* th = theta + base_off;
    float* po = out + base_off;
    float* pb = g_beta + base_off;

    if (w < 4) {
        // ====================== FORWARD (alpha) ======================
        const int s = w;
        const int col = s * 32 + lane;
        const int off = col * 3;
        float pm = NEGC, px = NEGC, py = NEGC;
        float dM = NEGC, dX = NEGC, dY = NEGC;   // boundary triple of row i-1 (regs)
        float la0 = NEGC, la1 = NEGC, la2 = NEGC;

        float t0 = th[off], t1 = th[off + 1], t2 = th[off + 2];
        for (int i = 0; i < 128; i++) {
            float n0, n1, n2;
            if (i < 127) {
                int r = (i + 1) * 384 + off;
                n0 = th[r]; n1 = th[r + 1]; n2 = th[r + 2];
            }

            // ---- S prefix-sum first (theta-only; issues while chain stalls) ----
            float d = t2 + A22;
            float S = d;
#pragma unroll
            for (int o = 1; o < 32; o <<= 1) {
                float tS = __shfl_up_sync(FULLMASK, S, o);
                if (lane >= o) S += tS;
            }

            // ---- shared-exp of own prev-row triple; v folds neighbor's lse3 ----
            float r0 = fmax3(pm, px, py);
            float Em = __expf(pm - r0), Ex = __expf(px - r0), Ey = __expf(py - r0);
            float dotM = fmaf(eM0, Em, fmaf(eM1, Ex, fmaf(eM2, Ey, FLR)));
            float dotX = fmaf(eX0, Em, fmaf(eX1, Ex, fmaf(eX2, Ey, FLR)));
            float v = r0 + __logf(dotM);             // = lse3 my right neighbor needs
            float x = t1 + r0 + __logf(dotX);

            float vsh = __shfl_up_sync(FULLMASK, v, 1);
            if (lane == 0) {
                if (s == 0) vsh = NEGC;
                else {
                    float rr = fmax3(dM, dX, dY);
                    float a0 = __expf(dM - rr), a1 = __expf(dX - rr), a2 = __expf(dY - rr);
                    vsh = rr + __logf(fmaf(eM0, a0, fmaf(eM1, a1, fmaf(eM2, a2, FLR))));
                }
                if (s == 0 && i == 0) vsh = 0.0f;    // start cell (0,0,match)
            }
            float m = t0 + vsh;

            float q = lse2(m + A02, x + A12);        // neighbor's c-source
            float qsh = __shfl_up_sync(FULLMASK, q, 1);
            float c = t2 + qsh;                      // lane0 garbage (excluded)

            float e = c - S;
            float em = (lane == 0) ? BIGNEG : e;
#pragma unroll
            for (int o = 16; o > 0; o >>= 1)
                em = fmaxf(em, __shfl_xor_sync(FULLMASK, em, o));
            float R = em;
            float Ee = (lane == 0) ? 0.0f : __expf(e - R);
            float ss = Ee;
#pragma unroll
            for (int o = 1; o < 32; o <<= 1) {
                float tS = __shfl_up_sync(FULLMASK, ss, o);
                if (lane >= o) ss += tS;
            }
            float bse = (lane == 0) ? NEGC : (R + __logf(ss + FLR));

            // ---------- LATE (needs mailbox slot i) ----------
            float hm = NEGC, hx = NEGC, hy = NEGC, hq = NEGC;
            if (s > 0) {
                if (acqload(&ff[s - 1][i]) == 0) {
                    while (acqload(&ff[s - 1][i]) == 0) { __nanosleep(32); }
                }
                hm = fm[s - 1][i]; hx = fx[s - 1][i];
                hy = fy[s - 1][i]; hq = fq[s - 1][i];
            }
            // y = S + LSE3(bse, hq - A22, hy)
            float qa = hq - A22;
            float rr2 = fmax3(bse, qa, hy);
            float y = S + rr2 + __logf(__expf(bse - rr2) + __expf(qa - rr2) + __expf(hy - rr2));

            int wo = i * 384 + off;
            po[wo] = m; po[wo + 1] = x; po[wo + 2] = y;

            if (s < 3 && lane == 31) {
                fm[s][i] = m; fx[s][i] = x; fy[s][i] = y; fq[s][i] = q;
                relstore(&ff[s][i], 1);
            }
            if (i == 127) { la0 = m; la1 = x; la2 = y; }

            pm = m; px = x; py = y;
            dM = hm; dX = hx; dY = hy;
            if (i < 127) { t0 = n0; t1 = n1; t2 = n2; }
        }
        if (s == 3) {   // logZ from alpha(127,127,:) held in lane 31
            la0 = __shfl_sync(FULLMASK, la0, 31);
            la1 = __shfl_sync(FULLMASK, la1, 31);
            la2 = __shfl_sync(FULLMASK, la2, 31);
            float r = fmax3(la0, la1, la2);
            float lz = r + __logf(__expf(la0 - r) + __expf(la1 - r) + __expf(la2 - r));
            if (lane == 31) shlogZ = lz;
        }
    } else {
        // ====================== BETA (independent lattice) ======================
        const int wl = w - 4;                 // 0..3
        const int v = 3 - wl;                 // v=0 is the rightmost (producer) seg
        const int col = 32 * wl + 31 - lane;  // scan pos p = 32v+lane -> col 127-p
        const int off = col * 3;
        float u0p = NEGC, u1p = NEGC;
        float u0ext = NEGC;                   // bu0s[v-1][i+1], carried in a reg

        float t0 = th[127 * 384 + off], t1 = th[127 * 384 + off + 1], t2 = th[127 * 384 + off + 2];
        for (int i = 127; i >= 0; i--) {
            float n0, n1, n2;
            if (i > 0) {
                int r = (i - 1) * 384 + off;
                n0 = th[r]; n1 = th[r + 1]; n2 = th[r + 2];
            }

            const bool lastcell = (v == 0 && lane == 0 && i == 127);

            // ---- S prefix-sum first (theta-only) ----
            float d = t2 + A22;
            if (lastcell) d = 0.0f;
            float S = d;
#pragma unroll
            for (int o = 1; o < 32; o <<= 1) {
                float tS = __shfl_up_sync(FULLMASK, S, o);
                if (lane >= o) S += tS;
            }

            float u0n = __shfl_up_sync(FULLMASK, u0p, 1);
            if (lane == 0) u0n = u0ext;       // v==0: stays NEGC

            float c = t2 + lse2(A20 + u0n, A21 + u1p);
            if (lastcell) c = t2;             // beta(127,127)=0

            float e = c - S;
            float em = e;
#pragma unroll
            for (int o = 16; o > 0; o >>= 1)
                em = fmaxf(em, __shfl_xor_sync(FULLMASK, em, o));
            float R = em;
            float Ee = __expf(e - R);
            float ss = Ee;
#pragma unroll
            for (int o = 1; o < 32; o <<= 1) {
                float tS = __shfl_up_sync(FULLMASK, ss, o);
                if (lane >= o) ss += tS;
            }
            float bse = R + __logf(ss + FLR);

            // ---------- LATE ----------
            float seed = NEGC, nexu0 = NEGC;
            if (v > 0) {
                if (acqload(&bf[v - 1][i]) == 0) {
                    while (acqload(&bf[v - 1][i]) == 0) { __nanosleep(32); }
                }
                seed  = bu2s[v - 1][i];
                nexu0 = bu0s[v - 1][i];       // becomes u0ext for row i-1
            }
            float y = S + lse2(bse, seed);    // inclusive u2 at this column
            float wr = __shfl_up_sync(FULLMASK, y, 1);
            if (lane == 0) wr = seed;         // exclusive (u2 at col j+1)

            float rr = fmax3(u0n, u1p, wr);
            float e0 = __expf(u0n - rr), e1 = __expf(u1p - rr), e2 = __expf(wr - rr);
            float bb0 = rr + __logf(fmaf(E[0], e0, fmaf(E[1], e1, fmaf(E[2], e2, FLR))));
            float bb1 = rr + __logf(fmaf(E[3], e0, fmaf(E[4], e1, fmaf(E[5], e2, FLR))));
            float bb2 = rr + __logf(fmaf(E[6], e0, fmaf(E[7], e1, fmaf(E[8], e2, FLR))));
            if (lastcell) { bb0 = 0.f; bb1 = 0.f; bb2 = 0.f; }

            int ro = i * 384 + off;
            pb[ro] = bb0; pb[ro + 1] = bb1; pb[ro + 2] = bb2;

            float nu0 = bb0 + t0;
            float nu1 = bb1 + t1;

            if (v < 3 && lane == 31) {
                bu0s[v][i] = nu0;
                bu2s[v][i] = y;
                relstore(&bf[v][i], 1);
            }
            u0p = nu0; u1p = nu1; u0ext = nexu0;
            if (i > 0) { t0 = n0; t1 = n1; t2 = n2; }
        }
    }

    // ====================== COMBINE ======================
    __syncthreads();
    const float lz = shlogZ;
    const float4* bp4 = reinterpret_cast<const float4*>(pb);
    float4* op4 = reinterpret_cast<float4*>(po);
#pragma unroll 4
    for (int t = tid; t < 12288; t += 256) {
        float4 a = op4[t];
        float4 bb = bp4[t];
        op4[t] = make_float4(a.x + bb.x - lz, a.y + bb.y - lz,
                             a.z + bb.z - lz, a.w + bb.w - lz);
    }
}

extern "C" void kernel_launch(void* const* d_in, const int* in_sizes, int n_in,
                              void* d_out, int out_size)
{
    const float* theta = (const float*)d_in[0];
    const float* A     = (const float*)d_in[1];
    float* out         = (float*)d_out;
    int B = in_sizes[1] / 9;   // 256
    fb_kernel<<<B, 256>>>(theta, A, out);
}

// round 14
// speedup vs baseline: 1.0191x; 1.0191x over previous
#include <cuda_runtime.h>

#define FULLMASK 0xffffffffu
#define NEGC (-1000000000.0f)
#define FLR  (1e-30f)
#define BIGNEG (-3.0e38f)

__device__ float g_beta[256 * 128 * 128 * 3];   // beta scratch (50.3 MB)

__device__ __forceinline__ float lse2(float a, float b) {
    float mx = fmaxf(a, b);
    float mn = fminf(a, b);
    return mx + __logf(1.0f + __expf(mn - mx));
}
__device__ __forceinline__ float fmax3(float a, float b, float c) {
    return fmaxf(fmaxf(a, b), c);
}
__device__ __forceinline__ void relstore(int* p, int v) {
    asm volatile("st.release.cta.b32 [%0], %1;" :: "l"(p), "r"(v) : "memory");
}
__device__ __forceinline__ int acqload(int* p) {
    int v; asm volatile("ld.acquire.cta.b32 %0, [%1];" : "=r"(v) : "l"(p) : "memory");
    return v;
}

// One CTA (8 warps) per batch. Warps 0-3: forward alpha (cols 32s..32s+31,
// 1 col/lane, left->right mailbox chain) -> out. Warps 4-7: beta lattice
// (independent), right->left chain -> g_beta. y-recurrence per row via
// softmax scan with a row-tracked exp reference (Rest = prev row's LSE,
// exact butterfly fallback while segment is cold). Then coalesced combine.
__global__ void __launch_bounds__(256, 1)
fb_kernel(const float* __restrict__ theta, const float* __restrict__ Aall,
          float* __restrict__ out)
{
    __shared__ float fm[3][128], fx[3][128], fy[3][128];   // fwd mailboxes
    __shared__ int   ff[3][128];
    __shared__ float bu0s[3][128], bu2s[3][128];           // beta mailboxes
    __shared__ int   bf[3][128];
    __shared__ float shlogZ;

    const int tid  = threadIdx.x;
    const int w    = tid >> 5;
    const int lane = tid & 31;
    const int b    = blockIdx.x;

    for (int j = tid; j < 3 * 128; j += 256) {
        (&ff[0][0])[j] = 0;
        (&bf[0][0])[j] = 0;
    }
    __syncthreads();

    const float* Ab = Aall + (size_t)b * 9;
    const float A02 = Ab[2], A12 = Ab[5], A20 = Ab[6], A21 = Ab[7], A22 = Ab[8];
    float E[9];
#pragma unroll
    for (int t = 0; t < 9; t++) E[t] = __expf(Ab[t]);
    const float eM0 = E[0], eM1 = E[3], eM2 = E[6];   // exp(A[:,0])
    const float eX0 = E[1], eX1 = E[4], eX2 = E[7];   // exp(A[:,1])

    const size_t base_off = (size_t)b * 49152;
    const float* th = theta + base_off;
    float* po = out + base_off;
    float* pb = g_beta + base_off;

    if (w < 4) {
        // ====================== FORWARD (alpha) ======================
        const int s = w;
        const int col = s * 32 + lane;
        const int off = col * 3;
        float pm = NEGC, px = NEGC, py = NEGC;
        float dM = NEGC, dX = NEGC, dY = NEGC;   // neighbor row i-1 boundary (regs)
        float la0 = NEGC, la1 = NEGC, la2 = NEGC;
        float Rest = BIGNEG;                     // exp reference (prev-row LSE)

        float t0 = th[off], t1 = th[off + 1], t2 = th[off + 2];
        for (int i = 0; i < 128; i++) {
            float n0, n1, n2;
            if (i < 127) {
                int r = (i + 1) * 384 + off;
                n0 = th[r]; n1 = th[r + 1]; n2 = th[r + 2];
            }

            // ---- S prefix-sum (theta-only) ----
            float d = t2 + A22;
            float S = d;
#pragma unroll
            for (int o = 1; o < 32; o <<= 1) {
                float tS = __shfl_up_sync(FULLMASK, S, o);
                if (lane >= o) S += tS;
            }

            // ---- shared-exp of own prev-row triple ----
            float r0 = fmax3(pm, px, py);
            float Em = __expf(pm - r0), Ex = __expf(px - r0), Ey = __expf(py - r0);
            float rs  = __shfl_up_sync(FULLMASK, r0, 1);
            float Ems = __shfl_up_sync(FULLMASK, Em, 1);
            float Exs = __shfl_up_sync(FULLMASK, Ex, 1);
            float Eys = __shfl_up_sync(FULLMASK, Ey, 1);
            if (lane == 0) {
                if (s == 0) { rs = NEGC; Ems = 0.f; Exs = 0.f; Eys = 0.f; }
                else {
                    rs = fmax3(dM, dX, dY);
                    Ems = __expf(dM - rs); Exs = __expf(dX - rs); Eys = __expf(dY - rs);
                }
            }

            float lm = rs + __logf(fmaf(eM0, Ems, fmaf(eM1, Exs, fmaf(eM2, Eys, FLR))));
            if (s == 0 && i == 0 && lane == 0) lm = 0.0f;   // start cell (0,0,match)
            float m = t0 + lm;
            float x = t1 + r0 + __logf(fmaf(eX0, Em, fmaf(eX1, Ex, fmaf(eX2, Ey, FLR))));

            float mnb = __shfl_up_sync(FULLMASK, m, 1);
            float xnb = __shfl_up_sync(FULLMASK, x, 1);
            float c = t2 + lse2(mnb + A02, xnb + A12);   // lane0 garbage (excluded)

            float e = c - S;
            if (Rest < -1.0e8f) {                 // cold segment: exact max
                float em = (lane == 0) ? BIGNEG : e;
#pragma unroll
                for (int o = 16; o > 0; o >>= 1)
                    em = fmaxf(em, __shfl_xor_sync(FULLMASK, em, o));
                Rest = em;
            }
            float Ee = (lane == 0) ? 0.0f : __expf(fminf(e - Rest, 85.0f));
            float ss = Ee;                        // prefix sum of exps
#pragma unroll
            for (int o = 1; o < 32; o <<= 1) {
                float tS = __shfl_up_sync(FULLMASK, ss, o);
                if (lane >= o) ss += tS;
            }
            float lsum = __logf(ss + FLR);
            float bseP = Rest + lsum;
            float bse = (lane == 0) ? NEGC : bseP;
            Rest = __shfl_sync(FULLMASK, bseP, 31);   // track for next row
            float t2b = __shfl_sync(FULLMASK, t2, 0); // lane0's theta_y

            // ---------- LATE (needs mailbox slot i) ----------
            float hm = NEGC, hx = NEGC, hy = NEGC;
            if (s > 0) {
                if (acqload(&ff[s - 1][i]) == 0) {
                    while (acqload(&ff[s - 1][i]) == 0) { __nanosleep(32); }
                }
                hm = fm[s - 1][i]; hx = fx[s - 1][i]; hy = fy[s - 1][i];
            }
            float c0 = t2b + lse2(hm + A02, hx + A12);    // lane0 cell, exact
            float aux = lse2(c0 - (t2b + A22), hy);       // e0 merged with seed
            float y = S + lse2(bse, aux);

            int wo = i * 384 + off;
            po[wo] = m; po[wo + 1] = x; po[wo + 2] = y;

            if (s < 3 && lane == 31) {
                fm[s][i] = m; fx[s][i] = x; fy[s][i] = y;
                relstore(&ff[s][i], 1);
            }
            if (i == 127) { la0 = m; la1 = x; la2 = y; }

            pm = m; px = x; py = y;
            dM = hm; dX = hx; dY = hy;
            if (i < 127) { t0 = n0; t1 = n1; t2 = n2; }
        }
        if (s == 3) {   // logZ from alpha(127,127,:) held in lane 31
            la0 = __shfl_sync(FULLMASK, la0, 31);
            la1 = __shfl_sync(FULLMASK, la1, 31);
            la2 = __shfl_sync(FULLMASK, la2, 31);
            float r = fmax3(la0, la1, la2);
            float lz = r + __logf(__expf(la0 - r) + __expf(la1 - r) + __expf(la2 - r));
            if (lane == 31) shlogZ = lz;
        }
    } else {
        // ====================== BETA (independent lattice) ======================
        const int wl = w - 4;                 // 0..3
        const int v = 3 - wl;                 // v=0 is the rightmost (producer) seg
        const int col = 32 * wl + 31 - lane;  // scan pos p = 32v+lane -> col 127-p
        const int off = col * 3;
        float u0p = NEGC, u1p = NEGC;
        float u0ext = NEGC;                   // bu0s[v-1][i+1], carried in a reg
        float Rest = BIGNEG;

        float t0 = th[127 * 384 + off], t1 = th[127 * 384 + off + 1], t2 = th[127 * 384 + off + 2];
        for (int i = 127; i >= 0; i--) {
            float n0, n1, n2;
            if (i > 0) {
                int r = (i - 1) * 384 + off;
                n0 = th[r]; n1 = th[r + 1]; n2 = th[r + 2];
            }

            const bool lastcell = (v == 0 && lane == 0 && i == 127);

            // ---- S prefix-sum (theta-only) ----
            float d = t2 + A22;
            if (lastcell) d = 0.0f;
            float S = d;
#pragma unroll
            for (int o = 1; o < 32; o <<= 1) {
                float tS = __shfl_up_sync(FULLMASK, S, o);
                if (lane >= o) S += tS;
            }

            float u0n = __shfl_up_sync(FULLMASK, u0p, 1);
            if (lane == 0) u0n = u0ext;       // v==0: stays NEGC

            float c = t2 + lse2(A20 + u0n, A21 + u1p);
            if (lastcell) c = t2;             // beta(127,127)=0

            float e = c - S;
            if (Rest < -1.0e8f) {             // cold segment: exact max
                float em = e;
#pragma unroll
                for (int o = 16; o > 0; o >>= 1)
                    em = fmaxf(em, __shfl_xor_sync(FULLMASK, em, o));
                Rest = em;
            }
            float Ee = __expf(fminf(e - Rest, 85.0f));
            float ss = Ee;
#pragma unroll
            for (int o = 1; o < 32; o <<= 1) {
                float tS = __shfl_up_sync(FULLMASK, ss, o);
                if (lane >= o) ss += tS;
            }
            float lsum = __logf(ss + FLR);
            float bse = Rest + lsum;
            Rest = __shfl_sync(FULLMASK, bse, 31);

            // ---------- LATE ----------
            float seed = NEGC, nexu0 = NEGC;
            if (v > 0) {
                if (acqload(&bf[v - 1][i]) == 0) {
                    while (acqload(&bf[v - 1][i]) == 0) { __nanosleep(32); }
                }
                seed  = bu2s[v - 1][i];
                nexu0 = bu0s[v - 1][i];       // becomes u0ext for row i-1
            }
            float y = S + lse2(bse, seed);    // inclusive u2 at this column
            float wr = __shfl_up_sync(FULLMASK, y, 1);
            if (lane == 0) wr = seed;         // exclusive (u2 at col j+1)

            float rr = fmax3(u0n, u1p, wr);
            float e0 = __expf(u0n - rr), e1 = __expf(u1p - rr), e2 = __expf(wr - rr);
            float bb0 = rr + __logf(fmaf(E[0], e0, fmaf(E[1], e1, fmaf(E[2], e2, FLR))));
            float bb1 = rr + __logf(fmaf(E[3], e0, fmaf(E[4], e1, fmaf(E[5], e2, FLR))));
            float bb2 = rr + __logf(fmaf(E[6], e0, fmaf(E[7], e1, fmaf(E[8], e2, FLR))));
            if (lastcell) { bb0 = 0.f; bb1 = 0.f; bb2 = 0.f; }

            int ro = i * 384 + off;
            pb[ro] = bb0; pb[ro + 1] = bb1; pb[ro + 2] = bb2;

            float nu0 = bb0 + t0;
            float nu1 = bb1 + t1;

            if (v < 3 && lane == 31) {
                bu0s[v][i] = nu0;
                bu2s[v][i] = y;
                relstore(&bf[v][i], 1);
            }
            u0p = nu0; u1p = nu1; u0ext = nexu0;
            if (i > 0) { t0 = n0; t1 = n1; t2 = n2; }
        }
    }

    // ====================== COMBINE ======================
    __syncthreads();
    const float lz = shlogZ;
    const float4* bp4 = reinterpret_cast<const float4*>(pb);
    float4* op4 = reinterpret_cast<float4*>(po);
#pragma unroll 4
    for (int t = tid; t < 12288; t += 256) {
        float4 a = op4[t];
        float4 bb = bp4[t];
        op4[t] = make_float4(a.x + bb.x - lz, a.y + bb.y - lz,
                             a.z + bb.z - lz, a.w + bb.w - lz);
    }
}

extern "C" void kernel_launch(void* const* d_in, const int* in_sizes, int n_in,
                              void* d_out, int out_size)
{
    const float* theta = (const float*)d_in[0];
    const float* A     = (const float*)d_in[1];
    float* out         = (float*)d_out;
    int B = in_sizes[1] / 9;   // 256
    fb_kernel<<<B, 256>>>(theta, A, out);
}